// round 15
// baseline (speedup 1.0000x reference)
#include <cuda_runtime.h>
#include <cuda_fp16.h>
#include <cstdint>

#define NN 32
#define PP 256
#define FF 256
#define BB 64
#define BC 512
#define OUTC 320
#define LOG2E 1.44269504088896340736f

// ---------------- device scratch ----------------
// p-major row layout: row = p*NN + n
__device__ __half g_Th[BC * FF];          // [n=512][k=256] fp16, pre-scaled by log2(e)
__device__ __half g_Xh[NN * PP * FF];     // [row=8192][k=256]

// ---------------- helpers ----------------
__device__ __forceinline__ uint32_t smem_u32(const void* p) {
    uint32_t a;
    asm("{ .reg .u64 t; cvta.to.shared.u64 t, %1; cvt.u32.u64 %0, t; }"
        : "=r"(a) : "l"(p));
    return a;
}

#define LDSM4(r, addr) \
    asm volatile("ldmatrix.sync.aligned.m8n8.x4.shared.b16 {%0,%1,%2,%3}, [%4];" \
        : "=r"((r)[0]), "=r"((r)[1]), "=r"((r)[2]), "=r"((r)[3]) : "r"(addr))

#define MMA_F16(c, a, b0, b1) \
    asm volatile("mma.sync.aligned.m16n8k16.row.col.f32.f16.f16.f32 " \
        "{%0,%1,%2,%3}, {%4,%5,%6,%7}, {%8,%9}, {%0,%1,%2,%3};" \
        : "+f"((c)[0]), "+f"((c)[1]), "+f"((c)[2]), "+f"((c)[3]) \
        : "r"((a)[0]), "r"((a)[1]), "r"((a)[2]), "r"((a)[3]), "r"(b0), "r"(b1))

__device__ __forceinline__ void cp16(uint32_t dst, const void* src) {
    asm volatile("cp.async.cg.shared.global [%0], [%1], 16;"
                 :: "r"(dst), "l"(src) : "memory");
}
#define CP_COMMIT() asm volatile("cp.async.commit_group;" ::: "memory")
#define CP_WAIT(n)  asm volatile("cp.async.wait_group %0;" :: "n"(n) : "memory")

__device__ __forceinline__ unsigned long long fma2(unsigned long long a,
                                                   unsigned long long b,
                                                   unsigned long long c) {
    unsigned long long d;
    asm("fma.rn.f32x2 %0, %1, %2, %3;" : "=l"(d) : "l"(a), "l"(b), "l"(c));
    return d;
}
__device__ __forceinline__ unsigned long long add2(unsigned long long a,
                                                   unsigned long long b) {
    unsigned long long d;
    asm("add.rn.f32x2 %0, %1, %2;" : "=l"(d) : "l"(a), "l"(b));
    return d;
}
__device__ __forceinline__ float ex2(float s) {
    float r;
    asm("ex2.approx.f32 %0, %1;" : "=f"(r) : "f"(s));
    return r;
}

// =============== prep: x -> fp16 (p-major) + passthrough; T transpose+scale ===============
__global__ __launch_bounds__(256)
void mbd_prep(const float* __restrict__ x, const float* __restrict__ T,
              float* __restrict__ out) {
    const int bid = blockIdx.x;
    const int t = threadIdx.x;
    if (bid < 256) {
        float4 v[8];
        int idx4[8];
        #pragma unroll
        for (int it = 0; it < 8; ++it) {
            idx4[it] = bid * 2048 + it * 256 + t;
            v[it] = *reinterpret_cast<const float4*>(x + (size_t)idx4[it] * 4);
        }
        #pragma unroll
        for (int it = 0; it < 8; ++it) {
            int r = idx4[it] >> 6;          // original row = n*PP + p
            int u = idx4[it] & 63;
            int n = r >> 8, p = r & 255;
            int rp = p * NN + n;            // p-major row
            *reinterpret_cast<float4*>(out + (size_t)r * OUTC + u * 4) = v[it];
            __half2 h0 = __floats2half2_rn(v[it].x, v[it].y);
            __half2 h1 = __floats2half2_rn(v[it].z, v[it].w);
            *reinterpret_cast<uint2*>(g_Xh + (size_t)rp * FF + u * 4) =
                make_uint2(*reinterpret_cast<uint32_t*>(&h0),
                           *reinterpret_cast<uint32_t*>(&h1));
        }
    } else {
        __shared__ float tile[32][33];
        const int b2 = bid - 256;           // 0..127
        const int f0 = (b2 & 7) * 32;
        const int n0 = (b2 >> 3) * 32;
        const int tx = t & 31;
        const int ty = t >> 5;
        #pragma unroll
        for (int r = 0; r < 4; ++r)
            tile[ty + 8 * r][tx] = T[(size_t)(f0 + ty + 8 * r) * BC + n0 + tx];
        __syncthreads();
        #pragma unroll
        for (int r = 0; r < 4; ++r) {
            int n = n0 + ty + 8 * r;
            int f = f0 + tx;
            g_Th[(size_t)n * FF + f] = __float2half(tile[tx][ty + 8 * r] * LOG2E);
        }
    }
}

// =============== fused GEMM (64x128x256, fp16 single) + symmetric pairwise ===============
#define PAD 72
#define SAH (64 * PAD)                      // A halves per stage
#define SBH (128 * PAD)                     // B halves per stage
#define STAGE_HALVES (SAH + SBH)            // 13824 halves = 27648 B
#define SMEM_FUSED (2 * STAGE_HALVES * 2)   // 55296 bytes
#define MROW 132                            // padded M row (floats)
#define OPART_OFF 33792                     // bytes: after Ms (64*132*4)

__global__ __launch_bounds__(256, 4)
void mbd_fused(float* __restrict__ out) {
    extern __shared__ __half sm[];
    const uint32_t smb = smem_u32(sm);
    float* Ms = reinterpret_cast<float*>(sm);   // reused after GEMM
    float* o_part = reinterpret_cast<float*>(
        reinterpret_cast<char*>(sm) + OPART_OFF);  // [32 grp][4 slot][32 i]
    const int t = threadIdx.x, w = t >> 5, lane = t & 31;
    const int bx = blockIdx.x;                  // 128 pixel-pairs
    const int by = blockIdx.y;                  // 4 col tiles (16 b each)
    const int mo = (w >> 2) * 32;
    const int no = (w & 3) * 32;

    float acc[2][4][4];
    #pragma unroll
    for (int i = 0; i < 2; ++i)
        #pragma unroll
        for (int j = 0; j < 4; ++j)
            #pragma unroll
            for (int e = 0; e < 4; ++e) acc[i][j][e] = 0.f;

    auto stage = [&](int kc, int s) {
        const uint32_t base = smb + (uint32_t)(s * STAGE_HALVES) * 2;
        // A: 64 rows x 64 halves = 512 cp16
        {
            int idx = t;
            int row = idx >> 3, u = idx & 7;
            cp16(base + (uint32_t)(row * PAD + u * 8) * 2,
                 g_Xh + (size_t)(bx * 64 + row) * FF + kc * 64 + u * 8);
            idx = t + 256;
            row = idx >> 3; u = idx & 7;
            cp16(base + (uint32_t)(row * PAD + u * 8) * 2,
                 g_Xh + (size_t)(bx * 64 + row) * FF + kc * 64 + u * 8);
        }
        // B: 128 rows x 64 halves = 1024 cp16
        #pragma unroll
        for (int it = 0; it < 4; ++it) {
            int idx = t + 256 * it;
            int row = idx >> 3, u = idx & 7;
            cp16(base + SAH * 2 + (uint32_t)(row * PAD + u * 8) * 2,
                 g_Th + (size_t)(by * 128 + row) * FF + kc * 64 + u * 8);
        }
        CP_COMMIT();
    };

    stage(0, 0);

    for (int kc = 0; kc < 4; ++kc) {
        if (kc < 3) stage(kc + 1, (kc + 1) & 1);
        if (kc < 3) { CP_WAIT(1); } else { CP_WAIT(0); }
        __syncthreads();

        const int s = kc & 1;
        const uint32_t a_base = smb + (uint32_t)(s * STAGE_HALVES) * 2;
        const uint32_t b_base = a_base + SAH * 2;

        #pragma unroll
        for (int ks = 0; ks < 4; ++ks) {
            uint32_t afh[2][4];
            #pragma unroll
            for (int mi = 0; mi < 2; ++mi) {
                uint32_t ad = a_base +
                    (uint32_t)(((mo + mi * 16 + (lane & 15)) * PAD) +
                               ks * 16 + (lane >> 4) * 8) * 2;
                LDSM4(afh[mi], ad);
            }
            uint32_t bf[8];
            #pragma unroll
            for (int g = 0; g < 2; ++g) {
                uint32_t bd = b_base +
                    (uint32_t)(((no + g * 16 + ((lane >> 4) & 1) * 8 + (lane & 7)) * PAD) +
                               ks * 16 + ((lane >> 3) & 1) * 8) * 2;
                LDSM4(&bf[g * 4], bd);
            }
            #pragma unroll
            for (int mi = 0; mi < 2; ++mi)
                #pragma unroll
                for (int ni = 0; ni < 4; ++ni)
                    MMA_F16(acc[mi][ni], afh[mi], bf[ni * 2], bf[ni * 2 + 1]);
        }
        __syncthreads();
    }

    // ---- epilogue: accumulators -> smem M tile [64 rows][MROW] ----
    #pragma unroll
    for (int mi = 0; mi < 2; ++mi)
        #pragma unroll
        for (int ni = 0; ni < 4; ++ni) {
            int col = no + ni * 8 + (lane & 3) * 2;
            #pragma unroll
            for (int h = 0; h < 2; ++h) {
                int row = mo + mi * 16 + (lane >> 2) + h * 8;
                *reinterpret_cast<float2*>(&Ms[row * MROW + col]) =
                    make_float2(acc[mi][ni][h * 2], acc[mi][ni][h * 2 + 1]);
            }
        }
    __syncthreads();

    // ---- symmetric pairwise L1 + exp2 (R8 scheme) ----
    const int p_l = t >> 7;
    const int rem = t & 127;
    const int b_l = rem >> 3;
    const int io  = rem & 7;
    const int grp = p_l * 16 + b_l;           // 0..31
    const unsigned long long NEG1 = 0xBF800000BF800000ULL;
    const unsigned long long AMSK = 0x7FFFFFFF7FFFFFFFULL;

    const int p_g = bx * 2 + p_l;
    const int b_g = by * 16 + b_l;

    unsigned long long mi[4][4];
    #pragma unroll
    for (int ii = 0; ii < 4; ++ii) {
        const ulonglong2* row = reinterpret_cast<const ulonglong2*>(
            &Ms[(p_l * 32 + io * 4 + ii) * MROW + b_l * 8]);
        ulonglong2 r0 = row[0], r1 = row[1];
        mi[ii][0] = r0.x; mi[ii][1] = r0.y;
        mi[ii][2] = r1.x; mi[ii][3] = r1.y;
    }
    float rowacc[4] = {0.f, 0.f, 0.f, 0.f};

    #pragma unroll
    for (int s = 0; s <= 4; ++s) {
        if (s == 4 && io >= 4) break;
        const int bblk = (io + s) & 7;
        float cacc[4] = {0.f, 0.f, 0.f, 0.f};
        #pragma unroll
        for (int jj = 0; jj < 4; ++jj) {
            const ulonglong2* row = reinterpret_cast<const ulonglong2*>(
                &Ms[(p_l * 32 + bblk * 4 + jj) * MROW + b_l * 8]);
            ulonglong2 r0 = row[0], r1 = row[1];
            unsigned long long jv0 = r0.x, jv1 = r0.y, jv2 = r1.x, jv3 = r1.y;
            #pragma unroll
            for (int ii = 0; ii < 4; ++ii) {
                unsigned long long d0 = fma2(jv0, NEG1, mi[ii][0]) & AMSK;
                unsigned long long d1 = fma2(jv1, NEG1, mi[ii][1]) & AMSK;
                unsigned long long d2 = fma2(jv2, NEG1, mi[ii][2]) & AMSK;
                unsigned long long d3 = fma2(jv3, NEG1, mi[ii][3]) & AMSK;
                unsigned long long s2 = add2(add2(d0, d1), add2(d2, d3));
                float sv = -__uint_as_float((uint32_t)s2) -
                            __uint_as_float((uint32_t)(s2 >> 32));
                float e = ex2(sv);
                rowacc[ii] += e;
                if (s) cacc[jj] += e;
            }
        }
        if (s) {
            float* dst = &o_part[(grp * 4 + (s - 1)) * 32 + bblk * 4];
            dst[0] = cacc[0]; dst[1] = cacc[1];
            dst[2] = cacc[2]; dst[3] = cacc[3];
        }
    }
    __syncthreads();

    #pragma unroll
    for (int ii = 0; ii < 4; ++ii) {
        int i = io * 4 + ii;
        float v = rowacc[ii]
                + o_part[(grp * 4 + 0) * 32 + i]
                + o_part[(grp * 4 + 1) * 32 + i]
                + o_part[(grp * 4 + 2) * 32 + i];
        if (io >= 4) v += o_part[(grp * 4 + 3) * 32 + i];
        out[(size_t)(i * PP + p_g) * OUTC + FF + b_g] = v;
    }
}

// =============== launch ===============
extern "C" void kernel_launch(void* const* d_in, const int* in_sizes, int n_in,
                              void* d_out, int out_size) {
    const float* x;
    const float* T;
    if (in_sizes[0] == NN * PP * FF) {
        x = (const float*)d_in[0];
        T = (const float*)d_in[1];
    } else {
        x = (const float*)d_in[1];
        T = (const float*)d_in[0];
    }
    float* out = (float*)d_out;

    cudaFuncSetAttribute(mbd_fused,
                         cudaFuncAttributeMaxDynamicSharedMemorySize, SMEM_FUSED);

    mbd_prep<<<256 + 128, 256>>>(x, T, out);
    mbd_fused<<<dim3(128, 4), 256, SMEM_FUSED>>>(out);
}

// round 16
// speedup vs baseline: 1.0691x; 1.0691x over previous
#include <cuda_runtime.h>
#include <cuda_fp16.h>
#include <cstdint>

#define NN 32
#define PP 256
#define FF 256
#define BB 64
#define BC 512
#define OUTC 320
#define LOG2E 1.44269504088896340736f

// ---------------- device scratch ----------------
// p-major row layout: row = p*NN + n
__device__ __half g_Th[BC * FF];          // [n=512][k=256] fp16, pre-scaled by log2(e)
__device__ __half g_Xh[NN * PP * FF];     // [row=8192][k=256]

// ---------------- helpers ----------------
__device__ __forceinline__ uint32_t smem_u32(const void* p) {
    uint32_t a;
    asm("{ .reg .u64 t; cvta.to.shared.u64 t, %1; cvt.u32.u64 %0, t; }"
        : "=r"(a) : "l"(p));
    return a;
}

#define LDSM4(r, addr) \
    asm volatile("ldmatrix.sync.aligned.m8n8.x4.shared.b16 {%0,%1,%2,%3}, [%4];" \
        : "=r"((r)[0]), "=r"((r)[1]), "=r"((r)[2]), "=r"((r)[3]) : "r"(addr))

#define MMA_F16(c, a, b0, b1) \
    asm volatile("mma.sync.aligned.m16n8k16.row.col.f32.f16.f16.f32 " \
        "{%0,%1,%2,%3}, {%4,%5,%6,%7}, {%8,%9}, {%0,%1,%2,%3};" \
        : "+f"((c)[0]), "+f"((c)[1]), "+f"((c)[2]), "+f"((c)[3]) \
        : "r"((a)[0]), "r"((a)[1]), "r"((a)[2]), "r"((a)[3]), "r"(b0), "r"(b1))

__device__ __forceinline__ void cp16(uint32_t dst, const void* src) {
    asm volatile("cp.async.cg.shared.global [%0], [%1], 16;"
                 :: "r"(dst), "l"(src) : "memory");
}
#define CP_COMMIT() asm volatile("cp.async.commit_group;" ::: "memory")
#define CP_WAIT(n)  asm volatile("cp.async.wait_group %0;" :: "n"(n) : "memory")

__device__ __forceinline__ unsigned long long fma2(unsigned long long a,
                                                   unsigned long long b,
                                                   unsigned long long c) {
    unsigned long long d;
    asm("fma.rn.f32x2 %0, %1, %2, %3;" : "=l"(d) : "l"(a), "l"(b), "l"(c));
    return d;
}
__device__ __forceinline__ unsigned long long add2(unsigned long long a,
                                                   unsigned long long b) {
    unsigned long long d;
    asm("add.rn.f32x2 %0, %1, %2;" : "=l"(d) : "l"(a), "l"(b));
    return d;
}
__device__ __forceinline__ float ex2(float s) {
    float r;
    asm("ex2.approx.f32 %0, %1;" : "=f"(r) : "f"(s));
    return r;
}

// =============== prep: x -> fp16 (p-major) + passthrough; T transpose+scale ===============
__global__ __launch_bounds__(256)
void mbd_prep(const float* __restrict__ x, const float* __restrict__ T,
              float* __restrict__ out) {
    const int bid = blockIdx.x;
    const int t = threadIdx.x;
    if (bid < 256) {
        float4 v[8];
        int idx4[8];
        #pragma unroll
        for (int it = 0; it < 8; ++it) {
            idx4[it] = bid * 2048 + it * 256 + t;
            v[it] = *reinterpret_cast<const float4*>(x + (size_t)idx4[it] * 4);
        }
        #pragma unroll
        for (int it = 0; it < 8; ++it) {
            int r = idx4[it] >> 6;          // original row = n*PP + p
            int u = idx4[it] & 63;
            int n = r >> 8, p = r & 255;
            int rp = p * NN + n;            // p-major row
            *reinterpret_cast<float4*>(out + (size_t)r * OUTC + u * 4) = v[it];
            __half2 h0 = __floats2half2_rn(v[it].x, v[it].y);
            __half2 h1 = __floats2half2_rn(v[it].z, v[it].w);
            *reinterpret_cast<uint2*>(g_Xh + (size_t)rp * FF + u * 4) =
                make_uint2(*reinterpret_cast<uint32_t*>(&h0),
                           *reinterpret_cast<uint32_t*>(&h1));
        }
    } else {
        __shared__ float tile[32][33];
        const int b2 = bid - 256;           // 0..127
        const int f0 = (b2 & 7) * 32;
        const int n0 = (b2 >> 3) * 32;
        const int tx = t & 31;
        const int ty = t >> 5;
        #pragma unroll
        for (int r = 0; r < 4; ++r)
            tile[ty + 8 * r][tx] = T[(size_t)(f0 + ty + 8 * r) * BC + n0 + tx];
        __syncthreads();
        #pragma unroll
        for (int r = 0; r < 4; ++r) {
            int n = n0 + ty + 8 * r;
            int f = f0 + tx;
            g_Th[(size_t)n * FF + f] = __float2half(tile[tx][ty + 8 * r] * LOG2E);
        }
    }
}

// =============== fused GEMM (64x128x256, fp16 single) + symmetric pairwise ===============
#define PAD 72
#define SAH (64 * PAD)                      // A halves per stage
#define SBH (128 * PAD)                     // B halves per stage
#define STAGE_HALVES (SAH + SBH)            // 13824 halves = 27648 B
#define SMEM_FUSED (2 * STAGE_HALVES * 2)   // 55296 bytes
#define MROW 132                            // padded M row (floats)
#define OPART_OFF 33792                     // bytes: after Ms (64*132*4)

__global__ __launch_bounds__(256, 3)
void mbd_fused(float* __restrict__ out) {
    extern __shared__ __half sm[];
    const uint32_t smb = smem_u32(sm);
    float* Ms = reinterpret_cast<float*>(sm);   // reused after GEMM
    float* o_part = reinterpret_cast<float*>(
        reinterpret_cast<char*>(sm) + OPART_OFF);  // [32 grp][4 slot][32 i]
    const int t = threadIdx.x, w = t >> 5, lane = t & 31;
    const int bx = blockIdx.x;                  // 128 pixel-pairs
    const int by = blockIdx.y;                  // 4 col tiles (16 b each)
    const int mo = (w >> 2) * 32;
    const int no = (w & 3) * 32;

    float acc[2][4][4];
    #pragma unroll
    for (int i = 0; i < 2; ++i)
        #pragma unroll
        for (int j = 0; j < 4; ++j)
            #pragma unroll
            for (int e = 0; e < 4; ++e) acc[i][j][e] = 0.f;

    auto stage = [&](int kc, int s) {
        const uint32_t base = smb + (uint32_t)(s * STAGE_HALVES) * 2;
        // A: 64 rows x 64 halves = 512 cp16
        {
            int idx = t;
            int row = idx >> 3, u = idx & 7;
            cp16(base + (uint32_t)(row * PAD + u * 8) * 2,
                 g_Xh + (size_t)(bx * 64 + row) * FF + kc * 64 + u * 8);
            idx = t + 256;
            row = idx >> 3; u = idx & 7;
            cp16(base + (uint32_t)(row * PAD + u * 8) * 2,
                 g_Xh + (size_t)(bx * 64 + row) * FF + kc * 64 + u * 8);
        }
        // B: 128 rows x 64 halves = 1024 cp16
        #pragma unroll
        for (int it = 0; it < 4; ++it) {
            int idx = t + 256 * it;
            int row = idx >> 3, u = idx & 7;
            cp16(base + SAH * 2 + (uint32_t)(row * PAD + u * 8) * 2,
                 g_Th + (size_t)(by * 128 + row) * FF + kc * 64 + u * 8);
        }
        CP_COMMIT();
    };

    stage(0, 0);

    for (int kc = 0; kc < 4; ++kc) {
        if (kc < 3) stage(kc + 1, (kc + 1) & 1);
        if (kc < 3) { CP_WAIT(1); } else { CP_WAIT(0); }
        __syncthreads();

        const int s = kc & 1;
        const uint32_t a_base = smb + (uint32_t)(s * STAGE_HALVES) * 2;
        const uint32_t b_base = a_base + SAH * 2;

        #pragma unroll
        for (int ks = 0; ks < 4; ++ks) {
            uint32_t afh[2][4];
            #pragma unroll
            for (int mi = 0; mi < 2; ++mi) {
                uint32_t ad = a_base +
                    (uint32_t)(((mo + mi * 16 + (lane & 15)) * PAD) +
                               ks * 16 + (lane >> 4) * 8) * 2;
                LDSM4(afh[mi], ad);
            }
            uint32_t bf[8];
            #pragma unroll
            for (int g = 0; g < 2; ++g) {
                uint32_t bd = b_base +
                    (uint32_t)(((no + g * 16 + ((lane >> 4) & 1) * 8 + (lane & 7)) * PAD) +
                               ks * 16 + ((lane >> 3) & 1) * 8) * 2;
                LDSM4(&bf[g * 4], bd);
            }
            #pragma unroll
            for (int mi = 0; mi < 2; ++mi)
                #pragma unroll
                for (int ni = 0; ni < 4; ++ni)
                    MMA_F16(acc[mi][ni], afh[mi], bf[ni * 2], bf[ni * 2 + 1]);
        }
        __syncthreads();
    }

    // ---- epilogue: accumulators -> smem M tile [64 rows][MROW] ----
    #pragma unroll
    for (int mi = 0; mi < 2; ++mi)
        #pragma unroll
        for (int ni = 0; ni < 4; ++ni) {
            int col = no + ni * 8 + (lane & 3) * 2;
            #pragma unroll
            for (int h = 0; h < 2; ++h) {
                int row = mo + mi * 16 + (lane >> 2) + h * 8;
                *reinterpret_cast<float2*>(&Ms[row * MROW + col]) =
                    make_float2(acc[mi][ni][h * 2], acc[mi][ni][h * 2 + 1]);
            }
        }
    __syncthreads();

    // ---- symmetric pairwise L1 + exp2 ----
    const int p_l = t >> 7;
    const int rem = t & 127;
    const int b_l = rem >> 3;
    const int io  = rem & 7;
    const int grp = p_l * 16 + b_l;           // 0..31
    const unsigned long long NEG1 = 0xBF800000BF800000ULL;
    const unsigned long long AMSK = 0x7FFFFFFF7FFFFFFFULL;

    const int p_g = bx * 2 + p_l;
    const int b_g = by * 16 + b_l;

    unsigned long long mi[4][4];
    #pragma unroll
    for (int ii = 0; ii < 4; ++ii) {
        const ulonglong2* row = reinterpret_cast<const ulonglong2*>(
            &Ms[(p_l * 32 + io * 4 + ii) * MROW + b_l * 8]);
        ulonglong2 r0 = row[0], r1 = row[1];
        mi[ii][0] = r0.x; mi[ii][1] = r0.y;
        mi[ii][2] = r1.x; mi[ii][3] = r1.y;
    }
    // self term exp(0)=1 per row
    float rowacc[4] = {1.f, 1.f, 1.f, 1.f};

    // ---- diagonal block (s=0): register-only, upper triangle, counted twice ----
    #pragma unroll
    for (int ii = 1; ii < 4; ++ii)
        #pragma unroll
        for (int jj = 0; jj < ii; ++jj) {
            unsigned long long d0 = fma2(mi[jj][0], NEG1, mi[ii][0]) & AMSK;
            unsigned long long d1 = fma2(mi[jj][1], NEG1, mi[ii][1]) & AMSK;
            unsigned long long d2 = fma2(mi[jj][2], NEG1, mi[ii][2]) & AMSK;
            unsigned long long d3 = fma2(mi[jj][3], NEG1, mi[ii][3]) & AMSK;
            unsigned long long s2 = add2(add2(d0, d1), add2(d2, d3));
            float sv = -__uint_as_float((uint32_t)s2) -
                        __uint_as_float((uint32_t)(s2 >> 32));
            float e = ex2(sv);
            rowacc[ii] += e;
            rowacc[jj] += e;
        }

    // ---- off-diagonal block-pairs s=1..4 ----
    #pragma unroll
    for (int s = 1; s <= 4; ++s) {
        if (s == 4 && io >= 4) break;
        const int bblk = (io + s) & 7;
        float cacc[4] = {0.f, 0.f, 0.f, 0.f};
        #pragma unroll
        for (int jj = 0; jj < 4; ++jj) {
            const ulonglong2* row = reinterpret_cast<const ulonglong2*>(
                &Ms[(p_l * 32 + bblk * 4 + jj) * MROW + b_l * 8]);
            ulonglong2 r0 = row[0], r1 = row[1];
            unsigned long long jv0 = r0.x, jv1 = r0.y, jv2 = r1.x, jv3 = r1.y;
            #pragma unroll
            for (int ii = 0; ii < 4; ++ii) {
                unsigned long long d0 = fma2(jv0, NEG1, mi[ii][0]) & AMSK;
                unsigned long long d1 = fma2(jv1, NEG1, mi[ii][1]) & AMSK;
                unsigned long long d2 = fma2(jv2, NEG1, mi[ii][2]) & AMSK;
                unsigned long long d3 = fma2(jv3, NEG1, mi[ii][3]) & AMSK;
                unsigned long long s2 = add2(add2(d0, d1), add2(d2, d3));
                float sv = -__uint_as_float((uint32_t)s2) -
                            __uint_as_float((uint32_t)(s2 >> 32));
                float e = ex2(sv);
                rowacc[ii] += e;
                cacc[jj] += e;
            }
        }
        float* dst = &o_part[(grp * 4 + (s - 1)) * 32 + bblk * 4];
        dst[0] = cacc[0]; dst[1] = cacc[1];
        dst[2] = cacc[2]; dst[3] = cacc[3];
    }
    __syncthreads();

    #pragma unroll
    for (int ii = 0; ii < 4; ++ii) {
        int i = io * 4 + ii;
        float v = rowacc[ii]
                + o_part[(grp * 4 + 0) * 32 + i]
                + o_part[(grp * 4 + 1) * 32 + i]
                + o_part[(grp * 4 + 2) * 32 + i];
        if (io >= 4) v += o_part[(grp * 4 + 3) * 32 + i];
        out[(size_t)(i * PP + p_g) * OUTC + FF + b_g] = v;
    }
}

// =============== launch ===============
extern "C" void kernel_launch(void* const* d_in, const int* in_sizes, int n_in,
                              void* d_out, int out_size) {
    const float* x;
    const float* T;
    if (in_sizes[0] == NN * PP * FF) {
        x = (const float*)d_in[0];
        T = (const float*)d_in[1];
    } else {
        x = (const float*)d_in[1];
        T = (const float*)d_in[0];
    }
    float* out = (float*)d_out;

    cudaFuncSetAttribute(mbd_fused,
                         cudaFuncAttributeMaxDynamicSharedMemorySize, SMEM_FUSED);

    mbd_prep<<<256 + 128, 256>>>(x, T, out);
    mbd_fused<<<dim3(128, 4), 256, SMEM_FUSED>>>(out);
}